// round 11
// baseline (speedup 1.0000x reference)
#include <cuda_runtime.h>
#include <cstdint>

#define BS   4
#define SEQ  128
#define DIM  768
#define HID  768
#define NOUT 2
#define MROWS (BS * SEQ)                    // 512
#define KSPLIT 384                          // K per split-K half

// ---------------- device scratch (no allocation allowed) -------------------
__device__ float g_ha[MROWS * HID];         // partial: a @ W1[:D], k-half 0
__device__ float g_hb[MROWS * HID];         // partial: b @ W1[D:] + b1, k-half 0
__device__ float g_ha2[MROWS * HID];        // partial k-half 1
__device__ float g_hb2[MROWS * HID];        // partial k-half 1

// ---------------------------------------------------------------------------
__device__ __forceinline__ uint32_t smem_u32(const void* p) {
    uint32_t a;
    asm("{ .reg .u64 t; cvta.to.shared.u64 t, %1; cvt.u32.u64 %0, t; }"
        : "=r"(a) : "l"(p));
    return a;
}

__device__ __forceinline__ void cp_async16(uint32_t saddr, const void* gptr) {
    asm volatile("cp.async.cg.shared.global [%0], [%1], 16;"
                 :: "r"(saddr), "l"(gptr) : "memory");
}
__device__ __forceinline__ void cp_commit() {
    asm volatile("cp.async.commit_group;" ::: "memory");
}
template <int N>
__device__ __forceinline__ void cp_wait() {
    asm volatile("cp.async.wait_group %0;" :: "n"(N) : "memory");
}

__device__ __forceinline__ uint32_t f2tf32(float x) {
    uint32_t u;
    asm("cvt.rna.tf32.f32 %0, %1;" : "=r"(u) : "f"(x));
    return u;
}

__device__ __forceinline__ void ldsm_x4(uint32_t* d, uint32_t saddr) {
    asm volatile(
        "ldmatrix.sync.aligned.m8n8.x4.shared.b16 {%0,%1,%2,%3}, [%4];"
        : "=r"(d[0]), "=r"(d[1]), "=r"(d[2]), "=r"(d[3]) : "r"(saddr));
}

__device__ __forceinline__ void mma_tf32(float* c, const uint32_t* a,
                                         const uint32_t* b) {
    asm volatile(
        "mma.sync.aligned.m16n8k8.row.col.f32.tf32.tf32.f32 "
        "{%0,%1,%2,%3}, {%4,%5,%6,%7}, {%8,%9}, {%0,%1,%2,%3};"
        : "+f"(c[0]), "+f"(c[1]), "+f"(c[2]), "+f"(c[3])
        : "r"(a[0]), "r"(a[1]), "r"(a[2]), "r"(a[3]), "r"(b[0]), "r"(b[1]));
}

// ---------------------------------------------------------------------------
// Kernel 1: projection GEMM (unchanged — proven ~10us).
// mma.sync tf32, split-K=2, BK=32, ldmatrix A fragments, in-reg cvt.rna.
// CTA tile 64x64, 128 threads, warp tile 32x32, 3-stage cp.async.
// Grid (12, 8, 4) = 384 CTAs. Dyn smem 55296 B.
// ---------------------------------------------------------------------------
#define ALD 36
#define BLD 72
#define STG_A (64 * ALD)
#define STG_B (32 * BLD)
#define PROJ_SMEM_BYTES (3 * (STG_A + STG_B) * 4)   // 55296

__global__ __launch_bounds__(128) void proj_tc(
    const float* __restrict__ a, const float* __restrict__ b,
    const float* __restrict__ W1, const float* __restrict__ b1)
{
    extern __shared__ float psm[];
    float* const Asm = psm;
    float* const Bsm = psm + 3 * STG_A;

    const int tid = threadIdx.x;
    const int wid = tid >> 5;
    const int lane = tid & 31;
    const int r = lane >> 2;
    const int c = lane & 3;
    const int wm = (wid >> 1) * 32;
    const int wn = (wid & 1) * 32;

    const int n0 = blockIdx.x * 64;
    const int m0 = blockIdx.y * 64;
    const int z  = blockIdx.z & 1;
    const int kh = blockIdx.z >> 1;
    const int kbase = kh * KSPLIT;

    const float* __restrict__ X = z ? b : a;
    const float* __restrict__ W = W1 + (size_t)z * DIM * HID;

    const uint32_t sA = smem_u32(Asm);
    const uint32_t sB = smem_u32(Bsm);

    const uint32_t a_lm0 =
        (uint32_t)(((wm + (lane & 7) + ((lane >> 3) & 1) * 8) * ALD
                    + ((lane >> 4) & 1) * 4) * 4);

    auto ldchunk = [&](int chunk, int s) {
        const int k0 = kbase + chunk * 32;
        #pragma unroll
        for (int i = 0; i < 4; i++) {
            int f = i * 128 + tid;
            int row = f >> 3, kc = (f & 7) * 4;
            cp_async16(sA + (uint32_t)(s * STG_A + row * ALD + kc) * 4,
                       X + (size_t)(m0 + row) * DIM + k0 + kc);
        }
        #pragma unroll
        for (int i = 0; i < 4; i++) {
            int f = i * 128 + tid;
            int kr = f >> 4, nc = (f & 15) * 4;
            cp_async16(sB + (uint32_t)(s * STG_B + kr * BLD + nc) * 4,
                       W + (size_t)(k0 + kr) * HID + n0 + nc);
        }
        cp_commit();
    };

    float acc[2][4][4] = {};

    ldchunk(0, 0);
    ldchunk(1, 1);

    for (int chunk = 0; chunk < 12; chunk++) {
        const int s = chunk % 3;
        if (chunk < 11) cp_wait<1>(); else cp_wait<0>();
        __syncthreads();

        if (chunk + 2 < 12) ldchunk(chunk + 2, (chunk + 2) % 3);

        const uint32_t aStage = sA + (uint32_t)(s * STG_A) * 4;
        const float* Bb = Bsm + s * STG_B;
        #pragma unroll
        for (int ks = 0; ks < 4; ks++) {
            const int kb = ks * 8;
            uint32_t af[2][4];
            #pragma unroll
            for (int mt = 0; mt < 2; mt++) {
                ldsm_x4(af[mt], aStage + a_lm0
                                + (uint32_t)(mt * 16 * ALD + kb) * 4);
                af[mt][0] = f2tf32(__uint_as_float(af[mt][0]));
                af[mt][1] = f2tf32(__uint_as_float(af[mt][1]));
                af[mt][2] = f2tf32(__uint_as_float(af[mt][2]));
                af[mt][3] = f2tf32(__uint_as_float(af[mt][3]));
            }
            uint32_t bf[4][2];
            #pragma unroll
            for (int nt = 0; nt < 4; nt++) {
                const float* bp = Bb + (kb + c) * BLD + wn + nt * 8 + r;
                bf[nt][0] = f2tf32(bp[0]);
                bf[nt][1] = f2tf32(bp[4 * BLD]);
            }
            #pragma unroll
            for (int nt = 0; nt < 4; nt++)
                #pragma unroll
                for (int mt = 0; mt < 2; mt++)
                    mma_tf32(acc[mt][nt], af[mt], bf[nt]);
        }
    }

    float* __restrict__ outp = z ? (kh ? g_hb2 : g_hb) : (kh ? g_ha2 : g_ha);
    const bool addb = (z == 1) && (kh == 0);
    #pragma unroll
    for (int mt = 0; mt < 2; mt++) {
        #pragma unroll
        for (int nt = 0; nt < 4; nt++) {
            int m = m0 + wm + mt * 16 + r;
            int n = n0 + wn + nt * 8 + c * 2;
            float2 v0 = make_float2(acc[mt][nt][0], acc[mt][nt][1]);
            float2 v1 = make_float2(acc[mt][nt][2], acc[mt][nt][3]);
            if (addb) {
                float2 bb = *(const float2*)&b1[n];
                v0.x += bb.x; v0.y += bb.y;
                v1.x += bb.x; v1.y += bb.y;
            }
            *(float2*)&outp[(size_t)m * HID + n] = v0;
            *(float2*)&outp[(size_t)(m + 8) * HID + n] = v1;
        }
    }
}

// ---------------------------------------------------------------------------
// Kernel 2 (RESTRUCTURED): pairwise relu + reduce to O=2.
// Tile 16s x 16t, grid (8, 8, 4) = 256 CTAs, 256 threads.
// 16 H-groups of 16 threads (48 h each, 3 chunks of 16 h).
// Thread tile 4s x 4t (s = sq+4i, t = tq+4j): per 4h, 10 LDS.128 feed
// 256 math ops with 32 independent acc chains. 4-step smem tree reduction.
// ---------------------------------------------------------------------------
#define HCI 16
__global__ __launch_bounds__(256) void pair_kernel(
    const float* __restrict__ W2, const float* __restrict__ b2,
    float* __restrict__ out)
{
    const int tt = blockIdx.x;              // t tile (16)
    const int st = blockIdx.y;              // s tile (16)
    const int batch = blockIdx.z;

    __shared__ float sha[16][16][20];       // [g][s][h]  (20480 B)
    __shared__ float shB[16][16][20];       // [g][t][h]  (20480 B)
    __shared__ float sw[16][40];            // [g][2h+o]  (2560 B)
    // reduction buffer aliased over sha (18432 B <= 20480 B)
    float (*red)[16][36] = reinterpret_cast<float (*)[16][36]>(&sha[0][0][0]);

    const int tid = threadIdx.x;
    const int g  = tid >> 4;                // 0..15 h-group
    const int lt = tid & 15;
    const int sq = lt >> 2;                 // 0..3
    const int tq = lt & 3;                  // 0..3

    const size_t rowS = (size_t)(batch * SEQ + st * 16) * HID;
    const size_t rowT = (size_t)(batch * SEQ + tt * 16) * HID;
    const float* __restrict__ hap  = g_ha  + rowS;
    const float* __restrict__ hap2 = g_ha2 + rowS;
    const float* __restrict__ hbp  = g_hb  + rowT;
    const float* __restrict__ hbp2 = g_hb2 + rowT;

    float acc[4][4][2] = {};                // [i][j][o]

    #pragma unroll 1
    for (int c = 0; c < 3; c++) {
        const int h0 = g * 48 + c * HCI;

        // fill: per group 16 rows x 16 h for A and B; 4 f4 per thread each
        #pragma unroll
        for (int q = 0; q < 4; q++) {
            int f = q * 16 + lt;
            int row = f >> 2, col = (f & 3) * 4;
            float4 u  = *(const float4*)&hap [(size_t)row * HID + h0 + col];
            float4 u2 = *(const float4*)&hap2[(size_t)row * HID + h0 + col];
            u.x += u2.x; u.y += u2.y; u.z += u2.z; u.w += u2.w;
            *(float4*)&sha[g][row][col] = u;
            float4 v  = *(const float4*)&hbp [(size_t)row * HID + h0 + col];
            float4 v2 = *(const float4*)&hbp2[(size_t)row * HID + h0 + col];
            v.x += v2.x; v.y += v2.y; v.z += v2.z; v.w += v2.w;
            *(float4*)&shB[g][row][col] = v;
        }
        if (lt < 8)
            *(float4*)&sw[g][lt * 4] = *(const float4*)&W2[h0 * 2 + lt * 4];
        __syncthreads();

        #pragma unroll
        for (int hh = 0; hh < HCI; hh += 4) {
            float4 A[4], B[4];
            #pragma unroll
            for (int i = 0; i < 4; i++)
                A[i] = *(const float4*)&sha[g][sq + 4 * i][hh];
            #pragma unroll
            for (int j = 0; j < 4; j++)
                B[j] = *(const float4*)&shB[g][tq + 4 * j][hh];
            float4 W0 = *(const float4*)&sw[g][2 * hh];
            float4 W1 = *(const float4*)&sw[g][2 * hh + 4];

            #pragma unroll
            for (int i = 0; i < 4; i++) {
                #pragma unroll
                for (int j = 0; j < 4; j++) {
                    float r;
                    r = fmaxf(A[i].x + B[j].x, 0.f);
                    acc[i][j][0] += r * W0.x; acc[i][j][1] += r * W0.y;
                    r = fmaxf(A[i].y + B[j].y, 0.f);
                    acc[i][j][0] += r * W0.z; acc[i][j][1] += r * W0.w;
                    r = fmaxf(A[i].z + B[j].z, 0.f);
                    acc[i][j][0] += r * W1.x; acc[i][j][1] += r * W1.y;
                    r = fmaxf(A[i].w + B[j].w, 0.f);
                    acc[i][j][0] += r * W1.z; acc[i][j][1] += r * W1.w;
                }
            }
        }
        __syncthreads();
    }

    // ---- 4-step tree reduction across the 16 h-groups ----
    float* af = (float*)acc;                // 32 floats
    // step 1: 16 -> 8
    if (g >= 8) {
        #pragma unroll
        for (int k = 0; k < 32; k += 4)
            *(float4*)&red[g - 8][lt][k] = *(const float4*)&af[k];
    }
    __syncthreads();
    if (g < 8) {
        #pragma unroll
        for (int k = 0; k < 32; k++) af[k] += red[g][lt][k];
    }
    __syncthreads();
    // step 2: 8 -> 4
    if (g >= 4 && g < 8) {
        #pragma unroll
        for (int k = 0; k < 32; k += 4)
            *(float4*)&red[g - 4][lt][k] = *(const float4*)&af[k];
    }
    __syncthreads();
    if (g < 4) {
        #pragma unroll
        for (int k = 0; k < 32; k++) af[k] += red[g][lt][k];
    }
    __syncthreads();
    // step 3: 4 -> 2
    if (g >= 2 && g < 4) {
        #pragma unroll
        for (int k = 0; k < 32; k += 4)
            *(float4*)&red[g - 2][lt][k] = *(const float4*)&af[k];
    }
    __syncthreads();
    if (g < 2) {
        #pragma unroll
        for (int k = 0; k < 32; k++) af[k] += red[g][lt][k];
    }
    __syncthreads();
    // step 4: 2 -> 1
    if (g == 1) {
        #pragma unroll
        for (int k = 0; k < 32; k += 4)
            *(float4*)&red[0][lt][k] = *(const float4*)&af[k];
    }
    __syncthreads();
    if (g == 0) {
        const float c0 = b2[0], c1 = b2[1];
        #pragma unroll
        for (int i = 0; i < 4; i++) {
            #pragma unroll
            for (int j = 0; j < 4; j++) {
                float v0 = acc[i][j][0] + red[0][lt][(i * 4 + j) * 2]     + c0;
                float v1 = acc[i][j][1] + red[0][lt][(i * 4 + j) * 2 + 1] + c1;
                int s = st * 16 + sq + 4 * i;
                int t = tt * 16 + tq + 4 * j;
                *(float2*)&out[(((size_t)batch * SEQ + s) * SEQ + t) * NOUT]
                    = make_float2(v0, v1);
            }
        }
    }
}

// ---------------------------------------------------------------------------
extern "C" void kernel_launch(void* const* d_in, const int* in_sizes, int n_in,
                              void* d_out, int out_size)
{
    const float* a  = (const float*)d_in[0];
    const float* b  = (const float*)d_in[1];
    const float* W1 = (const float*)d_in[2];
    const float* b1 = (const float*)d_in[3];
    const float* W2 = (const float*)d_in[4];
    const float* b2 = (const float*)d_in[5];
    float* out = (float*)d_out;

    cudaFuncSetAttribute(proj_tc, cudaFuncAttributeMaxDynamicSharedMemorySize,
                         PROJ_SMEM_BYTES);

    proj_tc<<<dim3(HID / 64, MROWS / 64, 4), 128, PROJ_SMEM_BYTES>>>(a, b, W1, b1);
    pair_kernel<<<dim3(SEQ / 16, SEQ / 16, BS), 256>>>(W2, b2, out);
}

// round 12
// speedup vs baseline: 1.1139x; 1.1139x over previous
#include <cuda_runtime.h>
#include <cstdint>

#define BS   4
#define SEQ  128
#define DIM  768
#define HID  768
#define NOUT 2
#define MROWS (BS * SEQ)                    // 512
#define KSPLIT 384                          // K per split-K half

// ---------------- device scratch (no allocation allowed) -------------------
__device__ float g_ha[MROWS * HID];         // partial: a @ W1[:D], k-half 0
__device__ float g_hb[MROWS * HID];         // partial: b @ W1[D:] + b1, k-half 0
__device__ float g_ha2[MROWS * HID];        // partial k-half 1
__device__ float g_hb2[MROWS * HID];        // partial k-half 1

// ---------------------------------------------------------------------------
__device__ __forceinline__ uint32_t smem_u32(const void* p) {
    uint32_t a;
    asm("{ .reg .u64 t; cvta.to.shared.u64 t, %1; cvt.u32.u64 %0, t; }"
        : "=r"(a) : "l"(p));
    return a;
}

__device__ __forceinline__ void cp_async16(uint32_t saddr, const void* gptr) {
    asm volatile("cp.async.cg.shared.global [%0], [%1], 16;"
                 :: "r"(saddr), "l"(gptr) : "memory");
}
__device__ __forceinline__ void cp_commit() {
    asm volatile("cp.async.commit_group;" ::: "memory");
}
template <int N>
__device__ __forceinline__ void cp_wait() {
    asm volatile("cp.async.wait_group %0;" :: "n"(N) : "memory");
}

__device__ __forceinline__ uint32_t f2tf32(float x) {
    uint32_t u;
    asm("cvt.rna.tf32.f32 %0, %1;" : "=r"(u) : "f"(x));
    return u;
}

__device__ __forceinline__ void ldsm_x4(uint32_t* d, uint32_t saddr) {
    asm volatile(
        "ldmatrix.sync.aligned.m8n8.x4.shared.b16 {%0,%1,%2,%3}, [%4];"
        : "=r"(d[0]), "=r"(d[1]), "=r"(d[2]), "=r"(d[3]) : "r"(saddr));
}

__device__ __forceinline__ void mma_tf32(float* c, const uint32_t* a,
                                         const uint32_t* b) {
    asm volatile(
        "mma.sync.aligned.m16n8k8.row.col.f32.tf32.tf32.f32 "
        "{%0,%1,%2,%3}, {%4,%5,%6,%7}, {%8,%9}, {%0,%1,%2,%3};"
        : "+f"(c[0]), "+f"(c[1]), "+f"(c[2]), "+f"(c[3])
        : "r"(a[0]), "r"(a[1]), "r"(a[2]), "r"(a[3]), "r"(b[0]), "r"(b[1]));
}

// ---------------------------------------------------------------------------
// Kernel 1: projection GEMM (unchanged — proven).
// mma.sync tf32, split-K=2, BK=32, ldmatrix A fragments, in-reg cvt.rna.
// CTA tile 64x64, 128 threads, warp tile 32x32, 3-stage cp.async.
// Grid (12, 8, 4) = 384 CTAs. Dyn smem 55296 B.
// ---------------------------------------------------------------------------
#define ALD 36
#define BLD 72
#define STG_A (64 * ALD)
#define STG_B (32 * BLD)
#define PROJ_SMEM_BYTES (3 * (STG_A + STG_B) * 4)   // 55296

__global__ __launch_bounds__(128) void proj_tc(
    const float* __restrict__ a, const float* __restrict__ b,
    const float* __restrict__ W1, const float* __restrict__ b1)
{
    extern __shared__ float psm[];
    float* const Asm = psm;
    float* const Bsm = psm + 3 * STG_A;

    const int tid = threadIdx.x;
    const int wid = tid >> 5;
    const int lane = tid & 31;
    const int r = lane >> 2;
    const int c = lane & 3;
    const int wm = (wid >> 1) * 32;
    const int wn = (wid & 1) * 32;

    const int n0 = blockIdx.x * 64;
    const int m0 = blockIdx.y * 64;
    const int z  = blockIdx.z & 1;
    const int kh = blockIdx.z >> 1;
    const int kbase = kh * KSPLIT;

    const float* __restrict__ X = z ? b : a;
    const float* __restrict__ W = W1 + (size_t)z * DIM * HID;

    const uint32_t sA = smem_u32(Asm);
    const uint32_t sB = smem_u32(Bsm);

    const uint32_t a_lm0 =
        (uint32_t)(((wm + (lane & 7) + ((lane >> 3) & 1) * 8) * ALD
                    + ((lane >> 4) & 1) * 4) * 4);

    auto ldchunk = [&](int chunk, int s) {
        const int k0 = kbase + chunk * 32;
        #pragma unroll
        for (int i = 0; i < 4; i++) {
            int f = i * 128 + tid;
            int row = f >> 3, kc = (f & 7) * 4;
            cp_async16(sA + (uint32_t)(s * STG_A + row * ALD + kc) * 4,
                       X + (size_t)(m0 + row) * DIM + k0 + kc);
        }
        #pragma unroll
        for (int i = 0; i < 4; i++) {
            int f = i * 128 + tid;
            int kr = f >> 4, nc = (f & 15) * 4;
            cp_async16(sB + (uint32_t)(s * STG_B + kr * BLD + nc) * 4,
                       W + (size_t)(k0 + kr) * HID + n0 + nc);
        }
        cp_commit();
    };

    float acc[2][4][4] = {};

    ldchunk(0, 0);
    ldchunk(1, 1);

    for (int chunk = 0; chunk < 12; chunk++) {
        const int s = chunk % 3;
        if (chunk < 11) cp_wait<1>(); else cp_wait<0>();
        __syncthreads();

        if (chunk + 2 < 12) ldchunk(chunk + 2, (chunk + 2) % 3);

        const uint32_t aStage = sA + (uint32_t)(s * STG_A) * 4;
        const float* Bb = Bsm + s * STG_B;
        #pragma unroll
        for (int ks = 0; ks < 4; ks++) {
            const int kb = ks * 8;
            uint32_t af[2][4];
            #pragma unroll
            for (int mt = 0; mt < 2; mt++) {
                ldsm_x4(af[mt], aStage + a_lm0
                                + (uint32_t)(mt * 16 * ALD + kb) * 4);
                af[mt][0] = f2tf32(__uint_as_float(af[mt][0]));
                af[mt][1] = f2tf32(__uint_as_float(af[mt][1]));
                af[mt][2] = f2tf32(__uint_as_float(af[mt][2]));
                af[mt][3] = f2tf32(__uint_as_float(af[mt][3]));
            }
            uint32_t bf[4][2];
            #pragma unroll
            for (int nt = 0; nt < 4; nt++) {
                const float* bp = Bb + (kb + c) * BLD + wn + nt * 8 + r;
                bf[nt][0] = f2tf32(bp[0]);
                bf[nt][1] = f2tf32(bp[4 * BLD]);
            }
            #pragma unroll
            for (int nt = 0; nt < 4; nt++)
                #pragma unroll
                for (int mt = 0; mt < 2; mt++)
                    mma_tf32(acc[mt][nt], af[mt], bf[nt]);
        }
    }

    float* __restrict__ outp = z ? (kh ? g_hb2 : g_hb) : (kh ? g_ha2 : g_ha);
    const bool addb = (z == 1) && (kh == 0);
    #pragma unroll
    for (int mt = 0; mt < 2; mt++) {
        #pragma unroll
        for (int nt = 0; nt < 4; nt++) {
            int m = m0 + wm + mt * 16 + r;
            int n = n0 + wn + nt * 8 + c * 2;
            float2 v0 = make_float2(acc[mt][nt][0], acc[mt][nt][1]);
            float2 v1 = make_float2(acc[mt][nt][2], acc[mt][nt][3]);
            if (addb) {
                float2 bb = *(const float2*)&b1[n];
                v0.x += bb.x; v0.y += bb.y;
                v1.x += bb.x; v1.y += bb.y;
            }
            *(float2*)&outp[(size_t)m * HID + n] = v0;
            *(float2*)&outp[(size_t)(m + 8) * HID + n] = v1;
        }
    }
}

// ---------------------------------------------------------------------------
// Kernel 2: pairwise relu + reduce to O=2 — ONE-WAVE version.
// Tile 32s x 16t, grid (8, 4, 4) = 128 CTAs (one full wave), 512 threads.
// 8 H-groups of 64 threads (96 h each, 3 chunks of 32 h).
// Thread tile 4s x 2t (s = sq+8i, t = tq+8j). Per 4h: 8 LDS.128 -> 128 ops,
// 16 acc chains. 3-step smem tree over groups; group 0 adds b2, writes out.
// Dynamic smem 57600 B (A | B | W; reduction aliased over A).
// ---------------------------------------------------------------------------
#define PLD 36                               // padded h stride (32 + 4)
#define PA_G (32 * PLD)                      // 1152 floats per group (A)
#define PB_G (16 * PLD)                      // 576  floats per group (B)
#define PB_BASE (8 * PA_G)                   // 9216
#define PW_BASE (PB_BASE + 8 * PB_G)         // 13824
#define PW_G 72                              // 64 + 8 pad
#define PAIR_SMEM_BYTES ((PW_BASE + 8 * PW_G) * 4)   // 57600

__global__ __launch_bounds__(512) void pair_kernel(
    const float* __restrict__ W2, const float* __restrict__ b2,
    float* __restrict__ out)
{
    extern __shared__ float sm[];

    const int tt = blockIdx.x;              // t tile (16 wide)
    const int st = blockIdx.y;              // s tile (32 wide)
    const int batch = blockIdx.z;

    const int tid = threadIdx.x;
    const int g  = tid >> 6;                // 0..7 h-group
    const int lt = tid & 63;
    const int sq = lt >> 3;                 // 0..7
    const int tq = lt & 7;                  // 0..7

    float* const sA = sm + g * PA_G;                 // [32][PLD]
    float* const sB = sm + PB_BASE + g * PB_G;       // [16][PLD]
    float* const sW = sm + PW_BASE + g * PW_G;       // [64]

    const size_t rowS = (size_t)(batch * SEQ + st * 32) * HID;
    const size_t rowT = (size_t)(batch * SEQ + tt * 16) * HID;
    const float* __restrict__ hap  = g_ha  + rowS;
    const float* __restrict__ hap2 = g_ha2 + rowS;
    const float* __restrict__ hbp  = g_hb  + rowT;
    const float* __restrict__ hbp2 = g_hb2 + rowT;

    float acc[4][2][2] = {};                // [i(s)][j(t)][o]

    #pragma unroll 1
    for (int c = 0; c < 3; c++) {
        const int h0 = g * 96 + c * 32;

        // A fill: 32 rows x 32 h = 256 f4, 4 per thread (h-coalesced)
        #pragma unroll
        for (int q = 0; q < 4; q++) {
            int f = q * 64 + lt;
            int row = f >> 3, col = (f & 7) * 4;
            float4 u  = *(const float4*)&hap [(size_t)row * HID + h0 + col];
            float4 u2 = *(const float4*)&hap2[(size_t)row * HID + h0 + col];
            u.x += u2.x; u.y += u2.y; u.z += u2.z; u.w += u2.w;
            *(float4*)&sA[row * PLD + col] = u;
        }
        // B fill: 16 rows x 32 h = 128 f4, 2 per thread
        #pragma unroll
        for (int q = 0; q < 2; q++) {
            int f = q * 64 + lt;
            int row = f >> 3, col = (f & 7) * 4;
            float4 v  = *(const float4*)&hbp [(size_t)row * HID + h0 + col];
            float4 v2 = *(const float4*)&hbp2[(size_t)row * HID + h0 + col];
            v.x += v2.x; v.y += v2.y; v.z += v2.z; v.w += v2.w;
            *(float4*)&sB[row * PLD + col] = v;
        }
        // W fill: 32 h x 2 outs = 16 f4
        if (lt < 16)
            *(float4*)&sW[lt * 4] = *(const float4*)&W2[h0 * 2 + lt * 4];
        __syncthreads();

        #pragma unroll
        for (int hh = 0; hh < 32; hh += 4) {
            float4 A[4], B[2];
            #pragma unroll
            for (int i = 0; i < 4; i++)
                A[i] = *(const float4*)&sA[(sq + 8 * i) * PLD + hh];
            #pragma unroll
            for (int j = 0; j < 2; j++)
                B[j] = *(const float4*)&sB[(tq + 8 * j) * PLD + hh];
            float4 W0 = *(const float4*)&sW[2 * hh];
            float4 W1 = *(const float4*)&sW[2 * hh + 4];

            #pragma unroll
            for (int i = 0; i < 4; i++) {
                #pragma unroll
                for (int j = 0; j < 2; j++) {
                    float r;
                    r = fmaxf(A[i].x + B[j].x, 0.f);
                    acc[i][j][0] += r * W0.x; acc[i][j][1] += r * W0.y;
                    r = fmaxf(A[i].y + B[j].y, 0.f);
                    acc[i][j][0] += r * W0.z; acc[i][j][1] += r * W0.w;
                    r = fmaxf(A[i].z + B[j].z, 0.f);
                    acc[i][j][0] += r * W1.x; acc[i][j][1] += r * W1.y;
                    r = fmaxf(A[i].w + B[j].w, 0.f);
                    acc[i][j][0] += r * W1.z; acc[i][j][1] += r * W1.w;
                }
            }
        }
        __syncthreads();
    }

    // ---- 3-step tree reduction across the 8 h-groups (alias over A) ----
    float (*red)[64][20] = reinterpret_cast<float (*)[64][20]>(sm);
    float* af = (float*)acc;                // 16 floats
    // 8 -> 4
    if (g >= 4) {
        #pragma unroll
        for (int k = 0; k < 16; k += 4)
            *(float4*)&red[g - 4][lt][k] = *(const float4*)&af[k];
    }
    __syncthreads();
    if (g < 4) {
        #pragma unroll
        for (int k = 0; k < 16; k++) af[k] += red[g][lt][k];
    }
    __syncthreads();
    // 4 -> 2
    if (g >= 2 && g < 4) {
        #pragma unroll
        for (int k = 0; k < 16; k += 4)
            *(float4*)&red[g - 2][lt][k] = *(const float4*)&af[k];
    }
    __syncthreads();
    if (g < 2) {
        #pragma unroll
        for (int k = 0; k < 16; k++) af[k] += red[g][lt][k];
    }
    __syncthreads();
    // 2 -> 1
    if (g == 1) {
        #pragma unroll
        for (int k = 0; k < 16; k += 4)
            *(float4*)&red[0][lt][k] = *(const float4*)&af[k];
    }
    __syncthreads();
    if (g == 0) {
        const float c0 = b2[0], c1 = b2[1];
        #pragma unroll
        for (int i = 0; i < 4; i++) {
            #pragma unroll
            for (int j = 0; j < 2; j++) {
                int k0i = (i * 2 + j) * 2;
                float v0 = acc[i][j][0] + red[0][lt][k0i]     + c0;
                float v1 = acc[i][j][1] + red[0][lt][k0i + 1] + c1;
                int s = st * 32 + sq + 8 * i;
                int t = tt * 16 + tq + 8 * j;
                *(float2*)&out[(((size_t)batch * SEQ + s) * SEQ + t) * NOUT]
                    = make_float2(v0, v1);
            }
        }
    }
}

// ---------------------------------------------------------------------------
extern "C" void kernel_launch(void* const* d_in, const int* in_sizes, int n_in,
                              void* d_out, int out_size)
{
    const float* a  = (const float*)d_in[0];
    const float* b  = (const float*)d_in[1];
    const float* W1 = (const float*)d_in[2];
    const float* b1 = (const float*)d_in[3];
    const float* W2 = (const float*)d_in[4];
    const float* b2 = (const float*)d_in[5];
    float* out = (float*)d_out;

    cudaFuncSetAttribute(proj_tc, cudaFuncAttributeMaxDynamicSharedMemorySize,
                         PROJ_SMEM_BYTES);
    cudaFuncSetAttribute(pair_kernel, cudaFuncAttributeMaxDynamicSharedMemorySize,
                         PAIR_SMEM_BYTES);

    proj_tc<<<dim3(HID / 64, MROWS / 64, 4), 128, PROJ_SMEM_BYTES>>>(a, b, W1, b1);
    pair_kernel<<<dim3(SEQ / 16, SEQ / 32, BS), 512, PAIR_SMEM_BYTES>>>(W2, b2, out);
}